// round 3
// baseline (speedup 1.0000x reference)
#include <cuda_runtime.h>

#define BATCH 2048
#define CELL 512
#define KDIM 30
#define LPAD 1024
#define VDIM 80

// scratch for alpha/beta/kappa: [B, 90], kappa pre-summed with kappa_old
__device__ float g_params[BATCH * 3 * KDIM];

// ---------------------------------------------------------------------------
// Kernel A: params = exp(x @ W.T + b); kappa = kappa_old + pre_kappa.
// 8 batches per block; x tile in smem; W streamed from L2 (256 block-reads).
// ---------------------------------------------------------------------------
__global__ __launch_bounds__(256) void params_kernel(
    const float* __restrict__ x,          // [B, CELL]
    const float* __restrict__ kappa_old,  // [B, K]
    const float* __restrict__ W,          // [3K, CELL]
    const float* __restrict__ bias,       // [3K]
    float* __restrict__ out_kappa)        // [B, K]
{
    __shared__ float4 xs[8 * CELL / 4];   // 16 KB

    const int tid = threadIdx.x;
    const int b0 = blockIdx.x * 8;

    const float4* xg = (const float4*)(x + (size_t)b0 * CELL);
    #pragma unroll
    for (int i = tid; i < 8 * CELL / 4; i += 256)
        xs[i] = xg[i];
    __syncthreads();

    // 720 outputs (8 batches x 90), ~3 per thread
    for (int oi = tid; oi < 8 * 3 * KDIM; oi += 256) {
        const int row = oi / (3 * KDIM);
        const int o   = oi - row * (3 * KDIM);
        const int b   = b0 + row;

        const float4* wrow = (const float4*)(W + (size_t)o * CELL);
        const float4* xr   = xs + row * (CELL / 4);
        float acc = 0.0f;
        #pragma unroll 8
        for (int j = 0; j < CELL / 4; j++) {
            float4 w4 = wrow[j];
            float4 x4 = xr[j];
            acc = fmaf(w4.x, x4.x, acc);
            acc = fmaf(w4.y, x4.y, acc);
            acc = fmaf(w4.z, x4.z, acc);
            acc = fmaf(w4.w, x4.w, acc);
        }
        float p = __expf(acc + bias[o]);
        if (o >= 2 * KDIM) {
            int k = o - 2 * KDIM;
            p += kappa_old[(size_t)b * KDIM + k];
            out_kappa[(size_t)b * KDIM + k] = p;
        }
        g_params[(size_t)b * (3 * KDIM) + o] = p;
    }
}

// ---------------------------------------------------------------------------
// Kernel B: fused phi + streaming w reduction.  One block per batch.
// ---------------------------------------------------------------------------
__global__ __launch_bounds__(256, 5) void phi_wsum_kernel(
    const float4* __restrict__ onehots,   // [B, L*V/4]
    const float* __restrict__ text_lens,  // [B, 1]
    float* __restrict__ out_w,            // [B, V]
    float* __restrict__ out_phi)          // [B, L+1]
{
    __shared__ float s_par[3 * KDIM];     // alpha | beta | kappa
    __shared__ float s_phi[LPAD];
    __shared__ float s_w[VDIM];

    const int bid = blockIdx.x;
    const int tid = threadIdx.x;

    if (tid < 3 * KDIM)
        s_par[tid] = g_params[(size_t)bid * (3 * KDIM) + tid];
    if (tid < VDIM) s_w[tid] = 0.0f;
    __syncthreads();

    const float scale = (float)LPAD / text_lens[bid];
    const float* s_alpha = s_par;
    const float* s_beta  = s_par + KDIM;
    const float* s_kappa = s_par + 2 * KDIM;

    for (int l = tid; l <= LPAD; l += 256) {
        const float fl = (float)l;
        float acc = 0.0f;
        #pragma unroll 5
        for (int k = 0; k < KDIM; k++) {
            float d = s_kappa[k] - fl;
            acc = fmaf(s_alpha[k], __expf(-s_beta[k] * d * d), acc);
        }
        float ph = acc * scale;
        out_phi[(size_t)bid * (LPAD + 1) + l] = ph;
        if (l < LPAD) s_phi[l] = ph;
    }
    __syncthreads();

    // Streaming reduction: per thread, float4 index tid + 256j; column base
    // has period 5 in j, row l advances +64 per 5-group.
    const float4* oh = onehots + (size_t)bid * (LPAD * VDIM / 4);

    float4 acc[5];
    int l0[5], cb[5];
    #pragma unroll
    for (int m = 0; m < 5; m++) {
        int e0 = 4 * tid + 1024 * m;
        l0[m] = e0 / VDIM;
        cb[m] = e0 % VDIM;
        acc[m] = make_float4(0.f, 0.f, 0.f, 0.f);
    }

    #pragma unroll 2
    for (int g = 0; g < 16; g++) {
        #pragma unroll
        for (int m = 0; m < 5; m++) {
            float4 v4 = __ldcs(&oh[tid + 256 * (m + 5 * g)]);
            float ph = s_phi[l0[m] + 64 * g];
            acc[m].x = fmaf(ph, v4.x, acc[m].x);
            acc[m].y = fmaf(ph, v4.y, acc[m].y);
            acc[m].z = fmaf(ph, v4.z, acc[m].z);
            acc[m].w = fmaf(ph, v4.w, acc[m].w);
        }
    }
    __syncthreads();

    #pragma unroll
    for (int m = 0; m < 5; m++) {
        atomicAdd(&s_w[cb[m] + 0], acc[m].x);
        atomicAdd(&s_w[cb[m] + 1], acc[m].y);
        atomicAdd(&s_w[cb[m] + 2], acc[m].z);
        atomicAdd(&s_w[cb[m] + 3], acc[m].w);
    }
    __syncthreads();

    if (tid < VDIM) out_w[(size_t)bid * VDIM + tid] = s_w[tid];
}

extern "C" void kernel_launch(void* const* d_in, const int* in_sizes, int n_in,
                              void* d_out, int out_size) {
    const float* x         = (const float*)d_in[0];
    const float* kappa_old = (const float*)d_in[1];
    const float4* onehots  = (const float4*)d_in[2];
    const float* text_lens = (const float*)d_in[3];
    const float* W         = (const float*)d_in[4];
    const float* bias      = (const float*)d_in[5];

    float* out = (float*)d_out;
    float* out_w     = out;                                  // [B, V]
    float* out_kappa = out + (size_t)BATCH * VDIM;           // [B, K]
    float* out_phi   = out + (size_t)BATCH * (VDIM + KDIM);  // [B, L+1]

    params_kernel<<<BATCH / 8, 256>>>(x, kappa_old, W, bias, out_kappa);
    phi_wsum_kernel<<<BATCH, 256>>>(onehots, text_lens, out_w, out_phi);
}

// round 4
// speedup vs baseline: 1.4796x; 1.4796x over previous
#include <cuda_runtime.h>

#define BATCH 2048
#define CELL 512
#define KDIM 30
#define LPAD 1024
#define VDIM 80

// scratch: [B, 90] = alpha | beta | kappa (kappa pre-summed with kappa_old)
__device__ float g_params[BATCH * 3 * KDIM];

// ---------------------------------------------------------------------------
// Kernel A: params = exp(x @ W.T + b).  4 batches per block, warp-per-output,
// 4 accumulators share each W load.  Low regs, no spills.
// ---------------------------------------------------------------------------
__global__ __launch_bounds__(256) void params_kernel(
    const float* __restrict__ x,          // [B, CELL]
    const float* __restrict__ kappa_old,  // [B, K]
    const float* __restrict__ W,          // [3K, CELL]
    const float* __restrict__ bias,       // [3K]
    float* __restrict__ out_kappa)        // [B, K]
{
    __shared__ float4 xs[4 * CELL / 4];   // 8 KB

    const int tid = threadIdx.x;
    const int wid = tid >> 5;
    const int lane = tid & 31;
    const int b0 = blockIdx.x * 4;

    const float4* xg = (const float4*)(x + (size_t)b0 * CELL);
    #pragma unroll
    for (int i = tid; i < 4 * CELL / 4; i += 256)
        xs[i] = xg[i];
    __syncthreads();

    for (int o = wid; o < 3 * KDIM; o += 8) {
        const float4* wrow = (const float4*)(W + (size_t)o * CELL);
        float a0 = 0.f, a1 = 0.f, a2 = 0.f, a3 = 0.f;
        #pragma unroll
        for (int j = 0; j < 4; j++) {
            float4 w4 = wrow[lane + 32 * j];
            float4 v;
            v = xs[0 * 128 + lane + 32 * j];
            a0 = fmaf(w4.x, v.x, fmaf(w4.y, v.y, fmaf(w4.z, v.z, fmaf(w4.w, v.w, a0))));
            v = xs[1 * 128 + lane + 32 * j];
            a1 = fmaf(w4.x, v.x, fmaf(w4.y, v.y, fmaf(w4.z, v.z, fmaf(w4.w, v.w, a1))));
            v = xs[2 * 128 + lane + 32 * j];
            a2 = fmaf(w4.x, v.x, fmaf(w4.y, v.y, fmaf(w4.z, v.z, fmaf(w4.w, v.w, a2))));
            v = xs[3 * 128 + lane + 32 * j];
            a3 = fmaf(w4.x, v.x, fmaf(w4.y, v.y, fmaf(w4.z, v.z, fmaf(w4.w, v.w, a3))));
        }
        #pragma unroll
        for (int off = 16; off; off >>= 1) {
            a0 += __shfl_xor_sync(0xffffffffu, a0, off);
            a1 += __shfl_xor_sync(0xffffffffu, a1, off);
            a2 += __shfl_xor_sync(0xffffffffu, a2, off);
            a3 += __shfl_xor_sync(0xffffffffu, a3, off);
        }
        if (lane < 4) {
            float acc = (lane == 0) ? a0 : (lane == 1) ? a1 : (lane == 2) ? a2 : a3;
            int b = b0 + lane;
            float p = __expf(acc + bias[o]);
            if (o >= 2 * KDIM) {
                int k = o - 2 * KDIM;
                p += kappa_old[(size_t)b * KDIM + k];
                out_kappa[(size_t)b * KDIM + k] = p;
            }
            g_params[(size_t)b * (3 * KDIM) + o] = p;
        }
    }
}

// ---------------------------------------------------------------------------
// Kernel B: sparse phi + streaming w reduction.  One block per batch.
// phi: each Gaussian only contributes where beta*(kappa-l)^2 < ~92
// (beyond that expf underflows to < 1e-38, matching fp32 reference ~ 0).
// ---------------------------------------------------------------------------
__global__ __launch_bounds__(256, 5) void phi_wsum_kernel(
    const float4* __restrict__ onehots,   // [B, L*V/4]
    const float* __restrict__ text_lens,  // [B, 1]
    float* __restrict__ out_w,            // [B, V]
    float* __restrict__ out_phi)          // [B, L+1]
{
    __shared__ float s_par[3 * KDIM];     // alpha | beta | kappa
    __shared__ float s_phi[LPAD + 1];
    __shared__ float s_w[VDIM];

    const int bid = blockIdx.x;
    const int tid = threadIdx.x;
    const int wid = tid >> 5;
    const int lane = tid & 31;

    if (tid < 3 * KDIM)
        s_par[tid] = g_params[(size_t)bid * (3 * KDIM) + tid];
    if (tid < VDIM) s_w[tid] = 0.0f;
    #pragma unroll
    for (int l = tid; l <= LPAD; l += 256)
        s_phi[l] = 0.0f;
    __syncthreads();

    // sparse Gaussian accumulation: one warp per mixture component
    for (int k = wid; k < KDIM; k += 8) {
        const float alpha = s_par[k];
        const float beta  = s_par[KDIM + k];
        const float kap   = s_par[2 * KDIM + k];
        const float r = fminf(sqrtf(92.0f / beta), 1100.0f);
        const int lo = max(0, (int)(kap - r));
        const int hi = min(LPAD, (int)(kap + r) + 1);
        for (int l = lo + lane; l <= hi; l += 32) {
            float d = kap - (float)l;
            atomicAdd(&s_phi[l], alpha * __expf(-beta * d * d));
        }
    }
    __syncthreads();

    const float scale = (float)LPAD / text_lens[bid];
    for (int l = tid; l <= LPAD; l += 256) {
        float ph = s_phi[l] * scale;
        out_phi[(size_t)bid * (LPAD + 1) + l] = ph;
        s_phi[l] = ph;
    }
    __syncthreads();

    // Streaming reduction: per thread, float4 index tid + 256j; column base
    // has period 5 in j, row l advances +64 per 5-group.
    const float4* oh = onehots + (size_t)bid * (LPAD * VDIM / 4);

    float4 acc[5];
    int l0[5], cb[5];
    #pragma unroll
    for (int m = 0; m < 5; m++) {
        int e0 = 4 * tid + 1024 * m;
        l0[m] = e0 / VDIM;
        cb[m] = e0 % VDIM;
        acc[m] = make_float4(0.f, 0.f, 0.f, 0.f);
    }

    #pragma unroll 2
    for (int g = 0; g < 16; g++) {
        #pragma unroll
        for (int m = 0; m < 5; m++) {
            float4 v4 = __ldcs(&oh[tid + 256 * (m + 5 * g)]);
            float ph = s_phi[l0[m] + 64 * g];
            acc[m].x = fmaf(ph, v4.x, acc[m].x);
            acc[m].y = fmaf(ph, v4.y, acc[m].y);
            acc[m].z = fmaf(ph, v4.z, acc[m].z);
            acc[m].w = fmaf(ph, v4.w, acc[m].w);
        }
    }
    __syncthreads();

    #pragma unroll
    for (int m = 0; m < 5; m++) {
        atomicAdd(&s_w[cb[m] + 0], acc[m].x);
        atomicAdd(&s_w[cb[m] + 1], acc[m].y);
        atomicAdd(&s_w[cb[m] + 2], acc[m].z);
        atomicAdd(&s_w[cb[m] + 3], acc[m].w);
    }
    __syncthreads();

    if (tid < VDIM) out_w[(size_t)bid * VDIM + tid] = s_w[tid];
}

extern "C" void kernel_launch(void* const* d_in, const int* in_sizes, int n_in,
                              void* d_out, int out_size) {
    const float* x         = (const float*)d_in[0];
    const float* kappa_old = (const float*)d_in[1];
    const float4* onehots  = (const float4*)d_in[2];
    const float* text_lens = (const float*)d_in[3];
    const float* W         = (const float*)d_in[4];
    const float* bias      = (const float*)d_in[5];

    float* out = (float*)d_out;
    float* out_w     = out;                                  // [B, V]
    float* out_kappa = out + (size_t)BATCH * VDIM;           // [B, K]
    float* out_phi   = out + (size_t)BATCH * (VDIM + KDIM);  // [B, L+1]

    params_kernel<<<BATCH / 4, 256>>>(x, kappa_old, W, bias, out_kappa);
    phi_wsum_kernel<<<BATCH, 256>>>(onehots, text_lens, out_w, out_phi);
}